// round 15
// baseline (speedup 1.0000x reference)
#include <cuda_runtime.h>
#include <math.h>

#define C 150
#define NBKT 300
#define D 128
#define GRID1 144
#define NMAX 2097152
#define TS 512                      // points per sort tile (one warp)
#define NSTEP (TS / 32)             // 16 steps per tile
#define TMAX (NMAX / TS)            // 4096
#define INVC 511u
#define INV_TEMP 5.0f
#define T1G 512                     // k1_gather threads
#define NW1 (T1G / 32)              // 16 warps
#define NSLOT (NW1 * 2)             // 32 staging slots

// ---- device scratch (fully re-written every launch) ----
__device__ unsigned short g_codes[NMAX];
__device__ unsigned short g_thist[TMAX * NBKT]; // per-tile histograms [t][b] (<=512)
__device__ unsigned short g_toffs[TMAX * NBKT]; // excl. tile prefix [t][b] (<=~7000)
__device__ int      g_total[NBKT];
__device__ int      g_base[NBKT + 1];
__device__ unsigned g_sorted[NMAX];            // point indices, stable-sorted by bucket
__device__ float    g_part1[GRID1 * NBKT * D]; // per-CTA partial slabs
__device__ float    g_ab[NBKT * D];            // normalized means
__device__ float    g_contrib[C];

// ---------------------------------------------------------------------------
// K0: encode codes + per-tile histograms. Histogram is order-independent:
// int4 loads (4 points/lane), ushort4 code store, shared atomicAdd into the
// warp's private 300-entry histogram. Pure streaming.
// ---------------------------------------------------------------------------
__global__ __launch_bounds__(256)
void k0_encode(const int* __restrict__ mask, const int* __restrict__ seg,
               const int* __restrict__ grp, int N, int T)
{
    __shared__ int shist[8][NBKT];
    const int wid = threadIdx.x >> 5, lane = threadIdx.x & 31;
    const int t = blockIdx.x * 8 + wid;
    if (t >= T) return;
    int* hist = shist[wid];
    for (int b = lane; b < NBKT; b += 32) hist[b] = 0;
    __syncwarp();

    const int p0 = t * TS;
    #pragma unroll
    for (int it = 0; it < TS / 128; it++) {
        const int base = p0 + it * 128 + lane * 4;   // 16B-aligned
        if (base + 4 <= N) {
            const int4 m = *(const int4*)(mask + base);
            const int4 s = *(const int4*)(seg  + base);
            const int4 g = *(const int4*)(grp  + base);
            unsigned c0 = (m.x > 0 && s.x != -1 && (unsigned)g.x <= 1u)
                        ? (unsigned)g.x * C + (unsigned)min(max(s.x, 0), C - 1) : INVC;
            unsigned c1 = (m.y > 0 && s.y != -1 && (unsigned)g.y <= 1u)
                        ? (unsigned)g.y * C + (unsigned)min(max(s.y, 0), C - 1) : INVC;
            unsigned c2 = (m.z > 0 && s.z != -1 && (unsigned)g.z <= 1u)
                        ? (unsigned)g.z * C + (unsigned)min(max(s.z, 0), C - 1) : INVC;
            unsigned c3 = (m.w > 0 && s.w != -1 && (unsigned)g.w <= 1u)
                        ? (unsigned)g.w * C + (unsigned)min(max(s.w, 0), C - 1) : INVC;
            ushort4 w;
            w.x = (unsigned short)c0; w.y = (unsigned short)c1;
            w.z = (unsigned short)c2; w.w = (unsigned short)c3;
            *(ushort4*)(g_codes + base) = w;
            if (c0 < NBKT) atomicAdd(&hist[c0], 1);
            if (c1 < NBKT) atomicAdd(&hist[c1], 1);
            if (c2 < NBKT) atomicAdd(&hist[c2], 1);
            if (c3 < NBKT) atomicAdd(&hist[c3], 1);
        } else {
            #pragma unroll
            for (int k = 0; k < 4; k++) {
                const int idx = base + k;
                if (idx < N) {
                    const int m = mask[idx], sv = seg[idx], g = grp[idx];
                    unsigned c = INVC;
                    if (m > 0 && sv != -1 && (unsigned)g <= 1u)
                        c = (unsigned)g * C + (unsigned)min(max(sv, 0), C - 1);
                    g_codes[idx] = (unsigned short)c;
                    if (c < NBKT) atomicAdd(&hist[c], 1);
                }
            }
        }
    }
    __syncwarp();
    for (int b = lane; b < NBKT; b += 32)
        g_thist[t * NBKT + b] = (unsigned short)hist[b];
}

// ---------------------------------------------------------------------------
// ScanA: per bucket b, exclusive prefix of g_thist over tiles; also totals.
// ---------------------------------------------------------------------------
__global__ __launch_bounds__(256)
void k_scanA(int T)
{
    __shared__ int sred[256];
    const int b = blockIdx.x, tid = threadIdx.x;
    const int per = (T + 255) / 256;
    const int t0 = tid * per;

    int lsum = 0;
    for (int i = 0; i < per; i++) {
        const int t = t0 + i;
        if (t < T) lsum += (int)g_thist[t * NBKT + b];
    }
    sred[tid] = lsum; __syncthreads();
    for (int off = 1; off < 256; off <<= 1) {
        const int v = (tid >= off) ? sred[tid - off] : 0;
        __syncthreads();
        sred[tid] += v;
        __syncthreads();
    }
    int run = (tid == 0) ? 0 : sred[tid - 1];
    if (tid == 255) g_total[b] = sred[255];
    for (int i = 0; i < per; i++) {
        const int t = t0 + i;
        if (t < T) {
            g_toffs[t * NBKT + b] = (unsigned short)run;
            run += (int)g_thist[t * NBKT + b];
        }
    }
}

// ---------------------------------------------------------------------------
// Base: exclusive scan over 300 bucket totals (+ grand total at g_base[NBKT]).
// ---------------------------------------------------------------------------
__global__ void k_base()
{
    if (threadIdx.x == 0) {
        int run = 0;
        for (int b = 0; b < NBKT; b++) { g_base[b] = run; run += g_total[b]; }
        g_base[NBKT] = run;
    }
}

// ---------------------------------------------------------------------------
// Scatter: stable counting-sort scatter. All 16 step codes preloaded into
// registers; per step the group LEADER does the ctr read-modify-write and
// broadcasts the old value via shfl -> short serial chain, 1 syncwarp/step.
// ---------------------------------------------------------------------------
__global__ __launch_bounds__(256)
void k_scatter(int N, int T)
{
    __shared__ int sctr[8][NBKT];
    const int wid = threadIdx.x >> 5, lane = threadIdx.x & 31;
    const int t = blockIdx.x * 8 + wid;
    if (t >= T) return;
    int* ctr = sctr[wid];
    for (int b = lane; b < NBKT; b += 32)
        ctr[b] = (int)g_toffs[t * NBKT + b] + g_base[b];
    __syncwarp();

    const int p0 = t * TS;

    unsigned short cs[NSTEP];
    #pragma unroll
    for (int k = 0; k < NSTEP; k++) {
        const int idx = p0 + k * 32 + lane;
        cs[k] = (idx < N) ? g_codes[idx] : (unsigned short)INVC;
    }

    #pragma unroll
    for (int k = 0; k < NSTEP; k++) {
        const int idx = p0 + k * 32 + lane;
        const unsigned c = cs[k];
        const unsigned mm = __match_any_sync(0xffffffffu, c);
        const int leader = __ffs(mm) - 1;
        const int rank = __popc(mm & ((1u << lane) - 1u));
        int ctrval = 0;
        if (lane == leader && c < NBKT) {
            ctrval = ctr[c];
            ctr[c] = ctrval + __popc(mm);
        }
        ctrval = __shfl_sync(0xffffffffu, ctrval, leader);
        if (c < NBKT) g_sorted[ctrval + rank] = (unsigned)idx;
        __syncwarp();
    }
}

// ---------------------------------------------------------------------------
// K1: register-accumulating gather over the sorted list, run-structured.
// 512 threads / 16 warps share one CTA accumulator (runs are exclusive).
// Hot loop: 16 statically-indexed LDG.128 per group (no spills), 4 indep
// accumulators, next index word prefetched. Boundary runs staged to slots,
// merged sequentially by warp 0 (deterministic, race-free).
// ---------------------------------------------------------------------------
__global__ __launch_bounds__(T1G, 1)
void k1_gather(const float* __restrict__ pred)
{
    extern __shared__ float sm[];
    float* acc   = sm;                          // [300][128]
    float* slots = sm + NBKT * D;               // [NSLOT][128]
    int*   smeta = (int*)(slots + NSLOT * D);   // [NSLOT]
    __shared__ int sbase[NBKT + 1];

    const int tid = threadIdx.x, wid = tid >> 5, lane = tid & 31;

    for (int i = tid; i < NBKT * D; i += T1G) acc[i] = 0.0f;
    if (tid < NSLOT) smeta[tid] = -1;
    for (int i = tid; i <= NBKT; i += T1G) sbase[i] = g_base[i];
    __syncthreads();

    const int M      = sbase[NBKT];
    const int perCTA = (M + GRID1 - 1) / GRID1;
    const int c0     = min(M, blockIdx.x * perCTA);
    const int c1     = min(M, c0 + perCTA);
    const int perW   = (c1 - c0 + NW1 - 1) / NW1;
    const int s0     = min(c1, c0 + wid * perW);
    const int s1     = min(c1, s0 + perW);

    int slotn = 0;
    int p = s0;
    while (p < s1) {
        // largest b with sbase[b] <= p
        int lo = 0, hi = NBKT;
        while (hi - lo > 1) { const int mid = (lo + hi) >> 1; if (sbase[mid] <= p) lo = mid; else hi = mid; }
        const int b    = lo;
        const int rend = min(s1, sbase[b + 1]);
        const int len  = rend - p;
        const int nf   = len >> 4;               // groups of 16 points
        const int mrem = len & 15;

        float4 a0 = make_float4(0.f,0.f,0.f,0.f), a1 = a0, a2 = a0, a3 = a0;

        unsigned e = 0;
        if (nf > 0) e = (lane < 16) ? g_sorted[p + lane] : 0u;
        for (int g = 0; g < nf; g++) {
            // prefetch next group's index word
            unsigned en = 0;
            if (g + 1 < nf) en = (lane < 16) ? g_sorted[p + (g + 1) * 16 + lane] : 0u;

            float4 v[16];
            #pragma unroll
            for (int k = 0; k < 16; k++) {
                const unsigned idx = __shfl_sync(0xffffffffu, e, k);
                v[k] = ((const float4*)(pred + (size_t)idx * D))[lane];
            }
            #pragma unroll
            for (int k = 0; k < 16; k += 4) {
                a0.x += v[k].x;   a0.y += v[k].y;   a0.z += v[k].z;   a0.w += v[k].w;
                a1.x += v[k+1].x; a1.y += v[k+1].y; a1.z += v[k+1].z; a1.w += v[k+1].w;
                a2.x += v[k+2].x; a2.y += v[k+2].y; a2.z += v[k+2].z; a2.w += v[k+2].w;
                a3.x += v[k+3].x; a3.y += v[k+3].y; a3.z += v[k+3].z; a3.w += v[k+3].w;
            }
            e = en;
        }
        if (mrem) {
            const int pt = p + nf * 16;
            const unsigned et = (lane < mrem) ? g_sorted[pt + lane] : 0u;
            #pragma unroll
            for (int k = 0; k < 16; k++) {
                const unsigned idx = __shfl_sync(0xffffffffu, et, k);
                const float4 v = ((const float4*)(pred + (size_t)idx * D))[lane];
                if (k < mrem) { a0.x += v.x; a0.y += v.y; a0.z += v.z; a0.w += v.w; }
            }
        }

        float4 t4;
        t4.x = (a0.x + a1.x) + (a2.x + a3.x);
        t4.y = (a0.y + a1.y) + (a2.y + a3.y);
        t4.z = (a0.z + a1.z) + (a2.z + a3.z);
        t4.w = (a0.w + a1.w) + (a2.w + a3.w);

        if (sbase[b] < s0 || sbase[b + 1] > s1) {          // boundary run: stage
            const int slot = wid * 2 + slotn;
            ((float4*)(slots + slot * D))[lane] = t4;
            if (lane == 0) smeta[slot] = b;
            slotn++;
        } else {                                           // interior run: exclusive
            ((float4*)(acc + b * D))[lane] = t4;
        }
        p = rend;
    }
    __syncthreads();

    if (wid == 0) {                                        // deterministic slot merge
        for (int s = 0; s < NSLOT; s++) {
            const int b = smeta[s];
            if (b >= 0) {
                const float4 sv = ((float4*)(slots + s * D))[lane];
                float4 a = ((float4*)(acc + b * D))[lane];
                a.x += sv.x; a.y += sv.y; a.z += sv.z; a.w += sv.w;
                ((float4*)(acc + b * D))[lane] = a;
            }
        }
    }
    __syncthreads();

    float* out = g_part1 + (size_t)blockIdx.x * (NBKT * D);
    for (int i = tid; i < NBKT * D; i += T1G) out[i] = acc[i];
}

// ---------------------------------------------------------------------------
// K2: reduce CTA slabs -> mean -> L2 normalize. grid = NBKT blocks, D threads.
// ---------------------------------------------------------------------------
__global__ void k2_mean_norm()
{
    __shared__ float red[D];
    const int gc = blockIdx.x;
    const int d  = threadIdx.x;
    const float cnt = fmaxf((float)g_total[gc], 1.0f);

    float s = 0.0f;
    for (int k = 0; k < GRID1; k++)
        s += g_part1[(size_t)k * (NBKT * D) + gc * D + d];
    const float mean = s / cnt;

    red[d] = mean * mean; __syncthreads();
    for (int s2 = 64; s2 > 0; s2 >>= 1) { if (d < s2) red[d] += red[d + s2]; __syncthreads(); }
    const float inv = rsqrtf(red[0]);

    g_ab[gc * D + d] = mean * inv;
}

// ---------------------------------------------------------------------------
// K3: block i computes logits row i AND column i (two 256-thread groups),
// then both logsumexps. grid = C blocks, 512 threads.
// ---------------------------------------------------------------------------
__global__ __launch_bounds__(512)
void k3_lse()
{
    extern __shared__ float s3[];
    float* aT  = s3;                 // [D][152]
    float* bT  = aT + D * 152;       // [D][152]
    float* ai  = bT + D * 152;       // [D]
    float* bi  = ai + D;             // [D]
    float* red = bi + D;             // [2][256]
    __shared__ float diag_s, lse_s[2];

    const int i = blockIdx.x, tid = threadIdx.x;
    const int g2 = tid >> 8;
    const int j  = tid & 255;

    for (int idx = tid; idx < C * D; idx += 512) {
        const int c = idx >> 7, d = idx & 127;
        aT[d * 152 + c] = g_ab[idx];
        bT[d * 152 + c] = g_ab[C * D + idx];
    }
    if (tid < D)            ai[tid] = g_ab[i * D + tid];
    else if (tid < 2 * D)   bi[tid - D] = g_ab[C * D + i * D + (tid - D)];
    __syncthreads();

    float x = -1e30f;
    if (j < C) {
        const float* vec = g2 ? bi : ai;
        const float* mat = g2 ? aT : bT;
        float xs = 0.0f;
        #pragma unroll 8
        for (int k = 0; k < D; k++) xs += vec[k] * mat[k * 152 + j];
        x = xs * INV_TEMP;
        if (g2 == 0 && j == i) diag_s = x;
    }

    red[tid] = x; __syncthreads();
    for (int s = 128; s > 0; s >>= 1) {
        if (j < s) red[tid] = fmaxf(red[tid], red[tid + s]);
        __syncthreads();
    }
    const float mx = red[g2 << 8]; __syncthreads();
    red[tid] = (j < C) ? expf(x - mx) : 0.0f; __syncthreads();
    for (int s = 128; s > 0; s >>= 1) {
        if (j < s) red[tid] += red[tid + s];
        __syncthreads();
    }
    if (j == 0) lse_s[g2] = mx + logf(red[g2 << 8]);
    __syncthreads();

    if (tid == 0) g_contrib[i] = lse_s[0] + lse_s[1] - 2.0f * diag_s;
}

// ---------------------------------------------------------------------------
// K4: final scalar.
// ---------------------------------------------------------------------------
__global__ void k4_final(float* __restrict__ out)
{
    __shared__ float red[256];
    const int tid = threadIdx.x;
    red[tid] = (tid < C) ? g_contrib[tid] : 0.0f; __syncthreads();
    for (int s = 128; s > 0; s >>= 1) { if (tid < s) red[tid] += red[tid + s]; __syncthreads(); }
    if (tid == 0) out[0] = red[0] * (1.0f / (2.0f * C));
}

// ---------------------------------------------------------------------------
extern "C" void kernel_launch(void* const* d_in, const int* in_sizes, int n_in,
                              void* d_out, int out_size)
{
    const float* pred = (const float*)d_in[0];
    // d_in[1] = target (unused by the loss math)
    const int* mask = (const int*)d_in[2];
    const int* seg  = (const int*)d_in[3];
    const int* grp  = (const int*)d_in[4];
    const int N = in_sizes[2];

    const int T   = (N + TS - 1) / TS;        // sort tiles
    const int nbl = (T + 7) / 8;              // 8 warp-tiles per block

    const size_t smem1 = (NBKT * D + NSLOT * D) * sizeof(float) + NSLOT * sizeof(int);
    cudaFuncSetAttribute(k1_gather, cudaFuncAttributeMaxDynamicSharedMemorySize, (int)smem1);
    const size_t smem3 = (2 * D * 152 + 2 * D + 512) * sizeof(float);
    cudaFuncSetAttribute(k3_lse, cudaFuncAttributeMaxDynamicSharedMemorySize, (int)smem3);

    k0_encode<<<nbl, 256>>>(mask, seg, grp, N, T);
    k_scanA<<<NBKT, 256>>>(T);
    k_base<<<1, 32>>>();
    k_scatter<<<nbl, 256>>>(N, T);
    k1_gather<<<GRID1, T1G, smem1>>>(pred);
    k2_mean_norm<<<NBKT, D>>>();
    k3_lse<<<C, 512, smem3>>>();
    k4_final<<<1, 256>>>((float*)d_out);
}

// round 16
// speedup vs baseline: 1.0264x; 1.0264x over previous
#include <cuda_runtime.h>
#include <math.h>

#define C 150
#define NBKT 300
#define D 128
#define GRID1 144
#define NMAX 2097152
#define TS 1024                     // points per sort tile (one warp)
#define NSTEP (TS / 32)             // 32 steps per tile
#define TMAX (NMAX / TS)            // 2048
#define INVC 511u
#define INV_TEMP 5.0f
#define T1G 512                     // k1_gather threads
#define NW1 (T1G / 32)              // 16 warps
#define NSLOT (NW1 * 2)             // 32 staging slots
#define K3ROWS 3                    // rows per k3 block (150 = 50*3)

// ---- device scratch (fully re-written every launch) ----
__device__ unsigned short g_codes[NMAX];
__device__ unsigned short g_thist[TMAX * NBKT]; // per-tile histograms (<=1024)
__device__ unsigned short g_toffs[TMAX * NBKT]; // excl. tile prefix (<= bucket total ~6.7K)
__device__ int      g_total[NBKT];
__device__ int      g_base[NBKT + 1];
__device__ unsigned g_sorted[NMAX];            // point indices, stable-sorted by bucket
__device__ float    g_part1[GRID1 * NBKT * D]; // per-CTA partial slabs
__device__ float    g_ab[NBKT * D];            // normalized means
__device__ float    g_contrib[C];

// ---------------------------------------------------------------------------
// K0: encode codes + per-tile histograms. Histogram is order-independent:
// int4 loads (4 points/lane), ushort4 code store, shared atomicAdd into the
// warp's private 300-entry histogram. Pure streaming.
// ---------------------------------------------------------------------------
__global__ __launch_bounds__(256)
void k0_encode(const int* __restrict__ mask, const int* __restrict__ seg,
               const int* __restrict__ grp, int N, int T)
{
    __shared__ int shist[8][NBKT];
    const int wid = threadIdx.x >> 5, lane = threadIdx.x & 31;
    const int t = blockIdx.x * 8 + wid;
    if (t >= T) return;
    int* hist = shist[wid];
    for (int b = lane; b < NBKT; b += 32) hist[b] = 0;
    __syncwarp();

    const int p0 = t * TS;
    #pragma unroll
    for (int it = 0; it < TS / 128; it++) {
        const int base = p0 + it * 128 + lane * 4;   // 16B-aligned
        if (base + 4 <= N) {
            const int4 m = *(const int4*)(mask + base);
            const int4 s = *(const int4*)(seg  + base);
            const int4 g = *(const int4*)(grp  + base);
            unsigned c0 = (m.x > 0 && s.x != -1 && (unsigned)g.x <= 1u)
                        ? (unsigned)g.x * C + (unsigned)min(max(s.x, 0), C - 1) : INVC;
            unsigned c1 = (m.y > 0 && s.y != -1 && (unsigned)g.y <= 1u)
                        ? (unsigned)g.y * C + (unsigned)min(max(s.y, 0), C - 1) : INVC;
            unsigned c2 = (m.z > 0 && s.z != -1 && (unsigned)g.z <= 1u)
                        ? (unsigned)g.z * C + (unsigned)min(max(s.z, 0), C - 1) : INVC;
            unsigned c3 = (m.w > 0 && s.w != -1 && (unsigned)g.w <= 1u)
                        ? (unsigned)g.w * C + (unsigned)min(max(s.w, 0), C - 1) : INVC;
            ushort4 w;
            w.x = (unsigned short)c0; w.y = (unsigned short)c1;
            w.z = (unsigned short)c2; w.w = (unsigned short)c3;
            *(ushort4*)(g_codes + base) = w;
            if (c0 < NBKT) atomicAdd(&hist[c0], 1);
            if (c1 < NBKT) atomicAdd(&hist[c1], 1);
            if (c2 < NBKT) atomicAdd(&hist[c2], 1);
            if (c3 < NBKT) atomicAdd(&hist[c3], 1);
        } else {
            #pragma unroll
            for (int k = 0; k < 4; k++) {
                const int idx = base + k;
                if (idx < N) {
                    const int m = mask[idx], sv = seg[idx], g = grp[idx];
                    unsigned c = INVC;
                    if (m > 0 && sv != -1 && (unsigned)g <= 1u)
                        c = (unsigned)g * C + (unsigned)min(max(sv, 0), C - 1);
                    g_codes[idx] = (unsigned short)c;
                    if (c < NBKT) atomicAdd(&hist[c], 1);
                }
            }
        }
    }
    __syncwarp();
    for (int b = lane; b < NBKT; b += 32)
        g_thist[t * NBKT + b] = (unsigned short)hist[b];
}

// ---------------------------------------------------------------------------
// ScanA: per bucket b, exclusive prefix of g_thist over tiles; also totals.
// ---------------------------------------------------------------------------
__global__ __launch_bounds__(256)
void k_scanA(int T)
{
    __shared__ int sred[256];
    const int b = blockIdx.x, tid = threadIdx.x;
    const int per = (T + 255) / 256;
    const int t0 = tid * per;

    int lsum = 0;
    for (int i = 0; i < per; i++) {
        const int t = t0 + i;
        if (t < T) lsum += (int)g_thist[t * NBKT + b];
    }
    sred[tid] = lsum; __syncthreads();
    for (int off = 1; off < 256; off <<= 1) {
        const int v = (tid >= off) ? sred[tid - off] : 0;
        __syncthreads();
        sred[tid] += v;
        __syncthreads();
    }
    int run = (tid == 0) ? 0 : sred[tid - 1];
    if (tid == 255) g_total[b] = sred[255];
    for (int i = 0; i < per; i++) {
        const int t = t0 + i;
        if (t < T) {
            g_toffs[t * NBKT + b] = (unsigned short)run;
            run += (int)g_thist[t * NBKT + b];
        }
    }
}

// ---------------------------------------------------------------------------
// Base: exclusive scan over 300 bucket totals (+ grand total at g_base[NBKT]).
// ---------------------------------------------------------------------------
__global__ void k_base()
{
    if (threadIdx.x == 0) {
        int run = 0;
        for (int b = 0; b < NBKT; b++) { g_base[b] = run; run += g_total[b]; }
        g_base[NBKT] = run;
    }
}

// ---------------------------------------------------------------------------
// Scatter: stable counting-sort scatter. All 32 step codes preloaded into
// registers; per step the group LEADER does the ctr read-modify-write and
// broadcasts the old value via shfl -> short serial chain, 1 syncwarp/step.
// ---------------------------------------------------------------------------
__global__ __launch_bounds__(256)
void k_scatter(int N, int T)
{
    __shared__ int sctr[8][NBKT];
    const int wid = threadIdx.x >> 5, lane = threadIdx.x & 31;
    const int t = blockIdx.x * 8 + wid;
    if (t >= T) return;
    int* ctr = sctr[wid];
    for (int b = lane; b < NBKT; b += 32)
        ctr[b] = (int)g_toffs[t * NBKT + b] + g_base[b];
    __syncwarp();

    const int p0 = t * TS;

    unsigned short cs[NSTEP];
    #pragma unroll
    for (int k = 0; k < NSTEP; k++) {
        const int idx = p0 + k * 32 + lane;
        cs[k] = (idx < N) ? g_codes[idx] : (unsigned short)INVC;
    }

    #pragma unroll
    for (int k = 0; k < NSTEP; k++) {
        const int idx = p0 + k * 32 + lane;
        const unsigned c = cs[k];
        const unsigned mm = __match_any_sync(0xffffffffu, c);
        const int leader = __ffs(mm) - 1;
        const int rank = __popc(mm & ((1u << lane) - 1u));
        int ctrval = 0;
        if (lane == leader && c < NBKT) {
            ctrval = ctr[c];
            ctr[c] = ctrval + __popc(mm);
        }
        ctrval = __shfl_sync(0xffffffffu, ctrval, leader);
        if (c < NBKT) g_sorted[ctrval + rank] = (unsigned)idx;
        __syncwarp();
    }
}

// ---------------------------------------------------------------------------
// K1: register-accumulating gather over the sorted list, run-structured.
// 512 threads / 16 warps share one CTA accumulator (runs are exclusive).
// Hot loop: 16 statically-indexed LDG.128 per group (no spills), 4 indep
// accumulators, next index word prefetched. Boundary runs staged to slots,
// merged sequentially by warp 0 (deterministic, race-free).
// ---------------------------------------------------------------------------
__global__ __launch_bounds__(T1G, 1)
void k1_gather(const float* __restrict__ pred)
{
    extern __shared__ float sm[];
    float* acc   = sm;                          // [300][128]
    float* slots = sm + NBKT * D;               // [NSLOT][128]
    int*   smeta = (int*)(slots + NSLOT * D);   // [NSLOT]
    __shared__ int sbase[NBKT + 1];

    const int tid = threadIdx.x, wid = tid >> 5, lane = tid & 31;

    for (int i = tid; i < NBKT * D; i += T1G) acc[i] = 0.0f;
    if (tid < NSLOT) smeta[tid] = -1;
    for (int i = tid; i <= NBKT; i += T1G) sbase[i] = g_base[i];
    __syncthreads();

    const int M      = sbase[NBKT];
    const int perCTA = (M + GRID1 - 1) / GRID1;
    const int c0     = min(M, blockIdx.x * perCTA);
    const int c1     = min(M, c0 + perCTA);
    const int perW   = (c1 - c0 + NW1 - 1) / NW1;
    const int s0     = min(c1, c0 + wid * perW);
    const int s1     = min(c1, s0 + perW);

    int slotn = 0;
    int p = s0;
    while (p < s1) {
        // largest b with sbase[b] <= p
        int lo = 0, hi = NBKT;
        while (hi - lo > 1) { const int mid = (lo + hi) >> 1; if (sbase[mid] <= p) lo = mid; else hi = mid; }
        const int b    = lo;
        const int rend = min(s1, sbase[b + 1]);
        const int len  = rend - p;
        const int nf   = len >> 4;               // groups of 16 points
        const int mrem = len & 15;

        float4 a0 = make_float4(0.f,0.f,0.f,0.f), a1 = a0, a2 = a0, a3 = a0;

        unsigned e = 0;
        if (nf > 0) e = (lane < 16) ? g_sorted[p + lane] : 0u;
        for (int g = 0; g < nf; g++) {
            // prefetch next group's index word
            unsigned en = 0;
            if (g + 1 < nf) en = (lane < 16) ? g_sorted[p + (g + 1) * 16 + lane] : 0u;

            float4 v[16];
            #pragma unroll
            for (int k = 0; k < 16; k++) {
                const unsigned idx = __shfl_sync(0xffffffffu, e, k);
                v[k] = ((const float4*)(pred + (size_t)idx * D))[lane];
            }
            #pragma unroll
            for (int k = 0; k < 16; k += 4) {
                a0.x += v[k].x;   a0.y += v[k].y;   a0.z += v[k].z;   a0.w += v[k].w;
                a1.x += v[k+1].x; a1.y += v[k+1].y; a1.z += v[k+1].z; a1.w += v[k+1].w;
                a2.x += v[k+2].x; a2.y += v[k+2].y; a2.z += v[k+2].z; a2.w += v[k+2].w;
                a3.x += v[k+3].x; a3.y += v[k+3].y; a3.z += v[k+3].z; a3.w += v[k+3].w;
            }
            e = en;
        }
        if (mrem) {
            const int pt = p + nf * 16;
            const unsigned et = (lane < mrem) ? g_sorted[pt + lane] : 0u;
            #pragma unroll
            for (int k = 0; k < 16; k++) {
                const unsigned idx = __shfl_sync(0xffffffffu, et, k);
                const float4 v = ((const float4*)(pred + (size_t)idx * D))[lane];
                if (k < mrem) { a0.x += v.x; a0.y += v.y; a0.z += v.z; a0.w += v.w; }
            }
        }

        float4 t4;
        t4.x = (a0.x + a1.x) + (a2.x + a3.x);
        t4.y = (a0.y + a1.y) + (a2.y + a3.y);
        t4.z = (a0.z + a1.z) + (a2.z + a3.z);
        t4.w = (a0.w + a1.w) + (a2.w + a3.w);

        if (sbase[b] < s0 || sbase[b + 1] > s1) {          // boundary run: stage
            const int slot = wid * 2 + slotn;
            ((float4*)(slots + slot * D))[lane] = t4;
            if (lane == 0) smeta[slot] = b;
            slotn++;
        } else {                                           // interior run: exclusive
            ((float4*)(acc + b * D))[lane] = t4;
        }
        p = rend;
    }
    __syncthreads();

    if (wid == 0) {                                        // deterministic slot merge
        for (int s = 0; s < NSLOT; s++) {
            const int b = smeta[s];
            if (b >= 0) {
                const float4 sv = ((float4*)(slots + s * D))[lane];
                float4 a = ((float4*)(acc + b * D))[lane];
                a.x += sv.x; a.y += sv.y; a.z += sv.z; a.w += sv.w;
                ((float4*)(acc + b * D))[lane] = a;
            }
        }
    }
    __syncthreads();

    float* out = g_part1 + (size_t)blockIdx.x * (NBKT * D);
    for (int i = tid; i < NBKT * D; i += T1G) out[i] = acc[i];
}

// ---------------------------------------------------------------------------
// K2: reduce CTA slabs -> mean -> L2 normalize. grid = NBKT blocks, D threads.
// ---------------------------------------------------------------------------
__global__ void k2_mean_norm()
{
    __shared__ float red[D];
    const int gc = blockIdx.x;
    const int d  = threadIdx.x;
    const float cnt = fmaxf((float)g_total[gc], 1.0f);

    float s = 0.0f;
    for (int k = 0; k < GRID1; k++)
        s += g_part1[(size_t)k * (NBKT * D) + gc * D + d];
    const float mean = s / cnt;

    red[d] = mean * mean; __syncthreads();
    for (int s2 = 64; s2 > 0; s2 >>= 1) { if (d < s2) red[d] += red[d + s2]; __syncthreads(); }
    const float inv = rsqrtf(red[0]);

    g_ab[gc * D + d] = mean * inv;
}

// ---------------------------------------------------------------------------
// K3: each block handles K3ROWS rows, reusing the SMEM-resident aT/bT across
// rows (amortizes the dominant redundant g_ab load 3x). Per row: logits row i
// AND column i in two 256-thread groups, then both logsumexps.
// grid = C/K3ROWS blocks, 512 threads.
// ---------------------------------------------------------------------------
__global__ __launch_bounds__(512)
void k3_lse()
{
    extern __shared__ float s3[];
    float* aT  = s3;                 // [D][152]
    float* bT  = aT + D * 152;       // [D][152]
    float* ai  = bT + D * 152;       // [D]
    float* bi  = ai + D;             // [D]
    float* red = bi + D;             // [2][256]
    __shared__ float diag_s, lse_s[2];

    const int tid = threadIdx.x;
    const int g2 = tid >> 8;
    const int j  = tid & 255;

    for (int idx = tid; idx < C * D; idx += 512) {
        const int c = idx >> 7, d = idx & 127;
        aT[d * 152 + c] = g_ab[idx];
        bT[d * 152 + c] = g_ab[C * D + idx];
    }
    __syncthreads();

    for (int r = 0; r < K3ROWS; r++) {
        const int i = blockIdx.x * K3ROWS + r;

        if (tid < D)            ai[tid] = g_ab[i * D + tid];
        else if (tid < 2 * D)   bi[tid - D] = g_ab[C * D + i * D + (tid - D)];
        __syncthreads();

        float x = -1e30f;
        if (j < C) {
            const float* vec = g2 ? bi : ai;
            const float* mat = g2 ? aT : bT;
            float xs = 0.0f;
            #pragma unroll 8
            for (int k = 0; k < D; k++) xs += vec[k] * mat[k * 152 + j];
            x = xs * INV_TEMP;
            if (g2 == 0 && j == i) diag_s = x;
        }

        red[tid] = x; __syncthreads();
        for (int s = 128; s > 0; s >>= 1) {
            if (j < s) red[tid] = fmaxf(red[tid], red[tid + s]);
            __syncthreads();
        }
        const float mx = red[g2 << 8]; __syncthreads();
        red[tid] = (j < C) ? expf(x - mx) : 0.0f; __syncthreads();
        for (int s = 128; s > 0; s >>= 1) {
            if (j < s) red[tid] += red[tid + s];
            __syncthreads();
        }
        if (j == 0) lse_s[g2] = mx + logf(red[g2 << 8]);
        __syncthreads();

        if (tid == 0) g_contrib[i] = lse_s[0] + lse_s[1] - 2.0f * diag_s;
        __syncthreads();
    }
}

// ---------------------------------------------------------------------------
// K4: final scalar.
// ---------------------------------------------------------------------------
__global__ void k4_final(float* __restrict__ out)
{
    __shared__ float red[256];
    const int tid = threadIdx.x;
    red[tid] = (tid < C) ? g_contrib[tid] : 0.0f; __syncthreads();
    for (int s = 128; s > 0; s >>= 1) { if (tid < s) red[tid] += red[tid + s]; __syncthreads(); }
    if (tid == 0) out[0] = red[0] * (1.0f / (2.0f * C));
}

// ---------------------------------------------------------------------------
extern "C" void kernel_launch(void* const* d_in, const int* in_sizes, int n_in,
                              void* d_out, int out_size)
{
    const float* pred = (const float*)d_in[0];
    // d_in[1] = target (unused by the loss math)
    const int* mask = (const int*)d_in[2];
    const int* seg  = (const int*)d_in[3];
    const int* grp  = (const int*)d_in[4];
    const int N = in_sizes[2];

    const int T   = (N + TS - 1) / TS;        // sort tiles
    const int nbl = (T + 7) / 8;              // 8 warp-tiles per block

    const size_t smem1 = (NBKT * D + NSLOT * D) * sizeof(float) + NSLOT * sizeof(int);
    cudaFuncSetAttribute(k1_gather, cudaFuncAttributeMaxDynamicSharedMemorySize, (int)smem1);
    const size_t smem3 = (2 * D * 152 + 2 * D + 512) * sizeof(float);
    cudaFuncSetAttribute(k3_lse, cudaFuncAttributeMaxDynamicSharedMemorySize, (int)smem3);

    k0_encode<<<nbl, 256>>>(mask, seg, grp, N, T);
    k_scanA<<<NBKT, 256>>>(T);
    k_base<<<1, 32>>>();
    k_scatter<<<nbl, 256>>>(N, T);
    k1_gather<<<GRID1, T1G, smem1>>>(pred);
    k2_mean_norm<<<NBKT, D>>>();
    k3_lse<<<C / K3ROWS, 512, smem3>>>();
    k4_final<<<1, 256>>>((float*)d_out);
}

// round 17
// speedup vs baseline: 1.0371x; 1.0104x over previous
#include <cuda_runtime.h>
#include <math.h>

#define C 150
#define NBKT 300
#define D 128
#define GRID1 144
#define NMAX 2097152
#define TS 1024                     // points per sort tile (one warp)
#define NSTEP (TS / 32)             // 32 steps per tile
#define TMAX (NMAX / TS)            // 2048
#define INVC 511u
#define INV_TEMP 5.0f
#define T1G 512                     // k1_gather threads
#define NW1 (T1G / 32)              // 16 warps
#define NSLOT (NW1 * 2)             // 32 staging slots
#define K3ROWS 3                    // rows per k3 block (150 = 50*3)
#define NREC (GRID1 * 2)            // boundary records

// ---- device scratch (fully re-written every launch) ----
__device__ unsigned short g_codes[NMAX];
__device__ int      g_thist[TMAX * NBKT];      // per-tile histograms [t][b]
__device__ int      g_toffs[TMAX * NBKT];      // exclusive tile prefix [t][b]
__device__ int      g_total[NBKT];
__device__ int      g_base[NBKT + 1];
__device__ unsigned g_sorted[NMAX];            // point indices, stable-sorted by bucket
__device__ float    g_sum[NBKT * D];           // final sums for CTA-exclusive buckets
__device__ int      g_btag[NREC];              // boundary record tags (-1 = unused)
__device__ float    g_bvec[NREC * D];          // boundary record vectors
__device__ float    g_ab[NBKT * D];            // normalized means
__device__ float    g_contrib[C];

// ---------------------------------------------------------------------------
// K0: encode codes + per-tile histograms. Histogram is order-independent:
// int4 loads (4 points/lane), ushort4 code store, shared atomicAdd into the
// warp's private 300-entry histogram. Pure streaming.
// ---------------------------------------------------------------------------
__global__ __launch_bounds__(256)
void k0_encode(const int* __restrict__ mask, const int* __restrict__ seg,
               const int* __restrict__ grp, int N, int T)
{
    __shared__ int shist[8][NBKT];
    const int wid = threadIdx.x >> 5, lane = threadIdx.x & 31;
    const int t = blockIdx.x * 8 + wid;
    if (t >= T) return;
    int* hist = shist[wid];
    for (int b = lane; b < NBKT; b += 32) hist[b] = 0;
    __syncwarp();

    const int p0 = t * TS;
    #pragma unroll
    for (int it = 0; it < TS / 128; it++) {
        const int base = p0 + it * 128 + lane * 4;   // 16B-aligned
        if (base + 4 <= N) {
            const int4 m = *(const int4*)(mask + base);
            const int4 s = *(const int4*)(seg  + base);
            const int4 g = *(const int4*)(grp  + base);
            unsigned c0 = (m.x > 0 && s.x != -1 && (unsigned)g.x <= 1u)
                        ? (unsigned)g.x * C + (unsigned)min(max(s.x, 0), C - 1) : INVC;
            unsigned c1 = (m.y > 0 && s.y != -1 && (unsigned)g.y <= 1u)
                        ? (unsigned)g.y * C + (unsigned)min(max(s.y, 0), C - 1) : INVC;
            unsigned c2 = (m.z > 0 && s.z != -1 && (unsigned)g.z <= 1u)
                        ? (unsigned)g.z * C + (unsigned)min(max(s.z, 0), C - 1) : INVC;
            unsigned c3 = (m.w > 0 && s.w != -1 && (unsigned)g.w <= 1u)
                        ? (unsigned)g.w * C + (unsigned)min(max(s.w, 0), C - 1) : INVC;
            ushort4 w;
            w.x = (unsigned short)c0; w.y = (unsigned short)c1;
            w.z = (unsigned short)c2; w.w = (unsigned short)c3;
            *(ushort4*)(g_codes + base) = w;
            if (c0 < NBKT) atomicAdd(&hist[c0], 1);
            if (c1 < NBKT) atomicAdd(&hist[c1], 1);
            if (c2 < NBKT) atomicAdd(&hist[c2], 1);
            if (c3 < NBKT) atomicAdd(&hist[c3], 1);
        } else {
            #pragma unroll
            for (int k = 0; k < 4; k++) {
                const int idx = base + k;
                if (idx < N) {
                    const int m = mask[idx], sv = seg[idx], g = grp[idx];
                    unsigned c = INVC;
                    if (m > 0 && sv != -1 && (unsigned)g <= 1u)
                        c = (unsigned)g * C + (unsigned)min(max(sv, 0), C - 1);
                    g_codes[idx] = (unsigned short)c;
                    if (c < NBKT) atomicAdd(&hist[c], 1);
                }
            }
        }
    }
    __syncwarp();
    for (int b = lane; b < NBKT; b += 32)
        g_thist[t * NBKT + b] = hist[b];
}

// ---------------------------------------------------------------------------
// ScanA: per bucket b, exclusive prefix of g_thist over tiles; also totals.
// Also zero-initializes g_sum[b] (cheap: block b owns it).
// ---------------------------------------------------------------------------
__global__ __launch_bounds__(256)
void k_scanA(int T)
{
    __shared__ int sred[256];
    const int b = blockIdx.x, tid = threadIdx.x;
    if (tid < D) g_sum[b * D + tid] = 0.0f;

    const int per = (T + 255) / 256;
    const int t0 = tid * per;

    int lsum = 0;
    for (int i = 0; i < per; i++) {
        const int t = t0 + i;
        if (t < T) lsum += g_thist[t * NBKT + b];
    }
    sred[tid] = lsum; __syncthreads();
    for (int off = 1; off < 256; off <<= 1) {
        const int v = (tid >= off) ? sred[tid - off] : 0;
        __syncthreads();
        sred[tid] += v;
        __syncthreads();
    }
    int run = (tid == 0) ? 0 : sred[tid - 1];
    if (tid == 255) g_total[b] = sred[255];
    for (int i = 0; i < per; i++) {
        const int t = t0 + i;
        if (t < T) {
            g_toffs[t * NBKT + b] = run;
            run += g_thist[t * NBKT + b];
        }
    }
}

// ---------------------------------------------------------------------------
// Base: exclusive scan over 300 bucket totals (+ grand total at g_base[NBKT]).
// ---------------------------------------------------------------------------
__global__ void k_base()
{
    if (threadIdx.x == 0) {
        int run = 0;
        for (int b = 0; b < NBKT; b++) { g_base[b] = run; run += g_total[b]; }
        g_base[NBKT] = run;
    }
}

// ---------------------------------------------------------------------------
// Scatter: stable counting-sort scatter. All 32 step codes preloaded into
// registers; per step the group LEADER does the ctr read-modify-write and
// broadcasts the old value via shfl -> short serial chain, 1 syncwarp/step.
// ---------------------------------------------------------------------------
__global__ __launch_bounds__(256)
void k_scatter(int N, int T)
{
    __shared__ int sctr[8][NBKT];
    const int wid = threadIdx.x >> 5, lane = threadIdx.x & 31;
    const int t = blockIdx.x * 8 + wid;
    if (t >= T) return;
    int* ctr = sctr[wid];
    for (int b = lane; b < NBKT; b += 32)
        ctr[b] = g_toffs[t * NBKT + b] + g_base[b];
    __syncwarp();

    const int p0 = t * TS;

    unsigned short cs[NSTEP];
    #pragma unroll
    for (int k = 0; k < NSTEP; k++) {
        const int idx = p0 + k * 32 + lane;
        cs[k] = (idx < N) ? g_codes[idx] : (unsigned short)INVC;
    }

    #pragma unroll
    for (int k = 0; k < NSTEP; k++) {
        const int idx = p0 + k * 32 + lane;
        const unsigned c = cs[k];
        const unsigned mm = __match_any_sync(0xffffffffu, c);
        const int leader = __ffs(mm) - 1;
        const int rank = __popc(mm & ((1u << lane) - 1u));
        int ctrval = 0;
        if (lane == leader && c < NBKT) {
            ctrval = ctr[c];
            ctr[c] = ctrval + __popc(mm);
        }
        ctrval = __shfl_sync(0xffffffffu, ctrval, leader);
        if (c < NBKT) g_sorted[ctrval + rank] = (unsigned)idx;
        __syncwarp();
    }
}

// ---------------------------------------------------------------------------
// K1: register-accumulating gather over the sorted list, run-structured.
// Each CTA's span touches only ~2-3 buckets: exclusive buckets write FINAL
// sums directly to g_sum; the <=2 CTA-boundary buckets emit tagged records.
// Hot loop identical to the proven R14 build (16 LDG.128/group, 4 indep
// accumulators, prefetched index words). Deterministic, race-free.
// ---------------------------------------------------------------------------
__global__ __launch_bounds__(T1G, 1)
void k1_gather(const float* __restrict__ pred)
{
    extern __shared__ float sm[];
    float* acc   = sm;                          // [300][128] (only touched rows used)
    float* slots = sm + NBKT * D;               // [NSLOT][128]
    int*   smeta = (int*)(slots + NSLOT * D);   // [NSLOT]
    __shared__ int sbase[NBKT + 1];

    const int tid = threadIdx.x, wid = tid >> 5, lane = tid & 31;

    if (tid < NSLOT) smeta[tid] = -1;
    for (int i = tid; i <= NBKT; i += T1G) sbase[i] = g_base[i];
    __syncthreads();

    const int M      = sbase[NBKT];
    const int perCTA = (M + GRID1 - 1) / GRID1;
    const int c0     = min(M, blockIdx.x * perCTA);
    const int c1     = min(M, c0 + perCTA);
    const int perW   = (c1 - c0 + NW1 - 1) / NW1;
    const int s0     = min(c1, c0 + wid * perW);
    const int s1     = min(c1, s0 + perW);

    // CTA bucket range (every thread computes; cheap)
    int firstB = -1, lastB = -2;
    if (c0 < c1) {
        int lo = 0, hi = NBKT;
        while (hi - lo > 1) { const int mid = (lo + hi) >> 1; if (sbase[mid] <= c0) lo = mid; else hi = mid; }
        firstB = lo;
        lo = 0; hi = NBKT;
        const int q = c1 - 1;
        while (hi - lo > 1) { const int mid = (lo + hi) >> 1; if (sbase[mid] <= q) lo = mid; else hi = mid; }
        lastB = lo;
    }
    // zero only the touched acc rows
    const int nrange = (lastB - firstB + 1) * D;
    for (int idx = tid; idx < nrange; idx += T1G) acc[firstB * D + idx] = 0.0f;
    __syncthreads();

    int slotn = 0;
    int p = s0;
    while (p < s1) {
        // largest b with sbase[b] <= p
        int lo = 0, hi = NBKT;
        while (hi - lo > 1) { const int mid = (lo + hi) >> 1; if (sbase[mid] <= p) lo = mid; else hi = mid; }
        const int b    = lo;
        const int rend = min(s1, sbase[b + 1]);
        const int len  = rend - p;
        const int nf   = len >> 4;               // groups of 16 points
        const int mrem = len & 15;

        float4 a0 = make_float4(0.f,0.f,0.f,0.f), a1 = a0, a2 = a0, a3 = a0;

        unsigned e = 0;
        if (nf > 0) e = (lane < 16) ? g_sorted[p + lane] : 0u;
        for (int g = 0; g < nf; g++) {
            unsigned en = 0;
            if (g + 1 < nf) en = (lane < 16) ? g_sorted[p + (g + 1) * 16 + lane] : 0u;

            float4 v[16];
            #pragma unroll
            for (int k = 0; k < 16; k++) {
                const unsigned idx = __shfl_sync(0xffffffffu, e, k);
                v[k] = ((const float4*)(pred + (size_t)idx * D))[lane];
            }
            #pragma unroll
            for (int k = 0; k < 16; k += 4) {
                a0.x += v[k].x;   a0.y += v[k].y;   a0.z += v[k].z;   a0.w += v[k].w;
                a1.x += v[k+1].x; a1.y += v[k+1].y; a1.z += v[k+1].z; a1.w += v[k+1].w;
                a2.x += v[k+2].x; a2.y += v[k+2].y; a2.z += v[k+2].z; a2.w += v[k+2].w;
                a3.x += v[k+3].x; a3.y += v[k+3].y; a3.z += v[k+3].z; a3.w += v[k+3].w;
            }
            e = en;
        }
        if (mrem) {
            const int pt = p + nf * 16;
            const unsigned et = (lane < mrem) ? g_sorted[pt + lane] : 0u;
            #pragma unroll
            for (int k = 0; k < 16; k++) {
                const unsigned idx = __shfl_sync(0xffffffffu, et, k);
                const float4 v = ((const float4*)(pred + (size_t)idx * D))[lane];
                if (k < mrem) { a0.x += v.x; a0.y += v.y; a0.z += v.z; a0.w += v.w; }
            }
        }

        float4 t4;
        t4.x = (a0.x + a1.x) + (a2.x + a3.x);
        t4.y = (a0.y + a1.y) + (a2.y + a3.y);
        t4.z = (a0.z + a1.z) + (a2.z + a3.z);
        t4.w = (a0.w + a1.w) + (a2.w + a3.w);

        if (sbase[b] < s0 || sbase[b + 1] > s1) {          // warp-boundary run: stage
            const int slot = wid * 2 + slotn;
            ((float4*)(slots + slot * D))[lane] = t4;
            if (lane == 0) smeta[slot] = b;
            slotn++;
        } else {                                           // warp-interior run: exclusive
            ((float4*)(acc + b * D))[lane] = t4;
        }
        p = rend;
    }
    __syncthreads();

    if (wid == 0) {                                        // deterministic slot merge
        for (int s = 0; s < NSLOT; s++) {
            const int b = smeta[s];
            if (b >= 0) {
                const float4 sv = ((float4*)(slots + s * D))[lane];
                float4 a = ((float4*)(acc + b * D))[lane];
                a.x += sv.x; a.y += sv.y; a.z += sv.z; a.w += sv.w;
                ((float4*)(acc + b * D))[lane] = a;
            }
        }
    }
    __syncthreads();

    // epilogue: exclusive buckets -> g_sum final; boundary buckets -> records
    const bool split0 = (firstB >= 0) && (sbase[firstB] < c0 || sbase[firstB + 1] > c1);
    const bool split1 = (lastB > firstB) && (sbase[lastB] < c0 || sbase[lastB + 1] > c1);
    if (tid == 0) {
        g_btag[blockIdx.x * 2]     = split0 ? firstB : -1;
        g_btag[blockIdx.x * 2 + 1] = split1 ? lastB  : -1;
    }
    if (tid < D) {
        if (split0) g_bvec[(blockIdx.x * 2) * D + tid] = acc[firstB * D + tid];
    } else if (tid < 2 * D) {
        const int d = tid - D;
        if (split1) g_bvec[(blockIdx.x * 2 + 1) * D + d] = acc[lastB * D + d];
    }
    for (int idx = tid; idx < nrange; idx += T1G) {
        const int b = firstB + (idx >> 7);
        if (sbase[b] >= c0 && sbase[b + 1] <= c1)
            g_sum[b * D + (idx & 127)] = acc[firstB * D + idx];
    }
}

// ---------------------------------------------------------------------------
// K2: g_sum + boundary records -> mean -> L2 normalize.
// grid = NBKT blocks, D threads. Records scanned in fixed CTA order.
// ---------------------------------------------------------------------------
__global__ void k2_mean_norm()
{
    __shared__ float red[D];
    __shared__ int stag[NREC];
    const int b = blockIdx.x;
    const int d = threadIdx.x;

    for (int r = d; r < NREC; r += D) stag[r] = g_btag[r];
    __syncthreads();

    float s = g_sum[b * D + d];
    for (int r = 0; r < NREC; r++)
        if (stag[r] == b) s += g_bvec[r * D + d];

    const float cnt = fmaxf((float)g_total[b], 1.0f);
    const float mean = s / cnt;

    red[d] = mean * mean; __syncthreads();
    for (int s2 = 64; s2 > 0; s2 >>= 1) { if (d < s2) red[d] += red[d + s2]; __syncthreads(); }
    const float inv = rsqrtf(red[0]);

    g_ab[b * D + d] = mean * inv;
}

// ---------------------------------------------------------------------------
// K3: each block handles K3ROWS rows, reusing SMEM-resident aT/bT across rows.
// Per row: logits row i AND column i in two 256-thread groups, then both
// logsumexps. grid = C/K3ROWS blocks, 512 threads.
// ---------------------------------------------------------------------------
__global__ __launch_bounds__(512)
void k3_lse()
{
    extern __shared__ float s3[];
    float* aT  = s3;                 // [D][152]
    float* bT  = aT + D * 152;       // [D][152]
    float* ai  = bT + D * 152;       // [D]
    float* bi  = ai + D;             // [D]
    float* red = bi + D;             // [2][256]
    __shared__ float diag_s, lse_s[2];

    const int tid = threadIdx.x;
    const int g2 = tid >> 8;
    const int j  = tid & 255;

    for (int idx = tid; idx < C * D; idx += 512) {
        const int c = idx >> 7, d = idx & 127;
        aT[d * 152 + c] = g_ab[idx];
        bT[d * 152 + c] = g_ab[C * D + idx];
    }
    __syncthreads();

    for (int r = 0; r < K3ROWS; r++) {
        const int i = blockIdx.x * K3ROWS + r;

        if (tid < D)            ai[tid] = g_ab[i * D + tid];
        else if (tid < 2 * D)   bi[tid - D] = g_ab[C * D + i * D + (tid - D)];
        __syncthreads();

        float x = -1e30f;
        if (j < C) {
            const float* vec = g2 ? bi : ai;
            const float* mat = g2 ? aT : bT;
            float xs = 0.0f;
            #pragma unroll 8
            for (int k = 0; k < D; k++) xs += vec[k] * mat[k * 152 + j];
            x = xs * INV_TEMP;
            if (g2 == 0 && j == i) diag_s = x;
        }

        red[tid] = x; __syncthreads();
        for (int s = 128; s > 0; s >>= 1) {
            if (j < s) red[tid] = fmaxf(red[tid], red[tid + s]);
            __syncthreads();
        }
        const float mx = red[g2 << 8]; __syncthreads();
        red[tid] = (j < C) ? expf(x - mx) : 0.0f; __syncthreads();
        for (int s = 128; s > 0; s >>= 1) {
            if (j < s) red[tid] += red[tid + s];
            __syncthreads();
        }
        if (j == 0) lse_s[g2] = mx + logf(red[g2 << 8]);
        __syncthreads();

        if (tid == 0) g_contrib[i] = lse_s[0] + lse_s[1] - 2.0f * diag_s;
        __syncthreads();
    }
}

// ---------------------------------------------------------------------------
// K4: final scalar.
// ---------------------------------------------------------------------------
__global__ void k4_final(float* __restrict__ out)
{
    __shared__ float red[256];
    const int tid = threadIdx.x;
    red[tid] = (tid < C) ? g_contrib[tid] : 0.0f; __syncthreads();
    for (int s = 128; s > 0; s >>= 1) { if (tid < s) red[tid] += red[tid + s]; __syncthreads(); }
    if (tid == 0) out[0] = red[0] * (1.0f / (2.0f * C));
}

// ---------------------------------------------------------------------------
extern "C" void kernel_launch(void* const* d_in, const int* in_sizes, int n_in,
                              void* d_out, int out_size)
{
    const float* pred = (const float*)d_in[0];
    // d_in[1] = target (unused by the loss math)
    const int* mask = (const int*)d_in[2];
    const int* seg  = (const int*)d_in[3];
    const int* grp  = (const int*)d_in[4];
    const int N = in_sizes[2];

    const int T   = (N + TS - 1) / TS;        // sort tiles
    const int nbl = (T + 7) / 8;              // 8 warp-tiles per block

    const size_t smem1 = (NBKT * D + NSLOT * D) * sizeof(float) + NSLOT * sizeof(int);
    cudaFuncSetAttribute(k1_gather, cudaFuncAttributeMaxDynamicSharedMemorySize, (int)smem1);
    const size_t smem3 = (2 * D * 152 + 2 * D + 512) * sizeof(float);
    cudaFuncSetAttribute(k3_lse, cudaFuncAttributeMaxDynamicSharedMemorySize, (int)smem3);

    k0_encode<<<nbl, 256>>>(mask, seg, grp, N, T);
    k_scanA<<<NBKT, 256>>>(T);
    k_base<<<1, 32>>>();
    k_scatter<<<nbl, 256>>>(N, T);
    k1_gather<<<GRID1, T1G, smem1>>>(pred);
    k2_mean_norm<<<NBKT, D>>>();
    k3_lse<<<C / K3ROWS, 512, smem3>>>();
    k4_final<<<1, 256>>>((float*)d_out);
}